// round 1
// baseline (speedup 1.0000x reference)
#include <cuda_runtime.h>
#include <cuda_bf16.h>

// Problem constants
#define B_MOLS 256
#define M_ATOMS 48
#define EDGES_PER_MOL (M_ATOMS * (M_ATOMS - 1))   // 2256
#define E_TOTAL (B_MOLS * EDGES_PER_MOL)          // 577536
#define N_ATOMS (B_MOLS * M_ATOMS)                // 12288
#define K_RBF 32
#define HS 128
#define NSH 25
#define FEAT_W 57                                  // 32 RBF + 25 SH

// Output layout (flattened reference tuple, float32)
#define OFF_FEAT 0ULL
#define OFF_EMB  ((size_t)E_TOTAL * FEAT_W)                    // 32919552
#define OFF_EI   (OFF_EMB + (size_t)N_ATOMS * HS)              // 34492416
#define OFF_TR   (OFF_EI + 2ULL * E_TOTAL)                     // 35647488

__device__ float g_logbinom[K_RBF];
__device__ float g_shcoef[NSH];

// ---------------------------------------------------------------------------
// Tiny init kernel: log C(31, v) and SH component-normalization coefficients.
// Runs every launch (deterministic), 1 warp, double precision.
// ---------------------------------------------------------------------------
__global__ void init_tables_kernel() {
    int t = threadIdx.x;
    if (t < K_RBF) {
        double lb = lgamma(32.0) - lgamma((double)t + 1.0) - lgamma(32.0 - (double)t);
        g_logbinom[t] = (float)lb;
    }
    if (t < NSH) {
        // j = l*l + l + m ; recover l, m
        int l = 0;
        while ((l + 1) * (l + 1) <= t) l++;
        int m = t - l * l - l;
        int am = m < 0 ? -m : m;
        double fr = 1.0;  // (l-am)! / (l+am)!
        for (int i = l - am + 1; i <= l + am; i++) fr /= (double)i;
        double c = sqrt((2.0 * l + 1.0) * fr);
        if (m != 0) c *= sqrt(2.0);
        g_shcoef[t] = (float)c;
    }
}

// ---------------------------------------------------------------------------
// Edge kernel: one thread = one edge. Computes RBF(32) + SH(25) into shared
// staging, plus edge_index / transpose_index (coalesced scalar stores), then
// block-cooperatively drains the 57-wide feature rows with float4 stores.
// ---------------------------------------------------------------------------
#define EPB 128

__global__ __launch_bounds__(EPB) void edge_kernel(
    const float* __restrict__ pos,
    const float* __restrict__ alpha,
    float* __restrict__ out)
{
    __shared__ float sfeat[EPB * FEAT_W];   // 29184 B

    const int e0 = blockIdx.x * EPB;
    const int e  = e0 + threadIdx.x;        // grid sized exactly: E % EPB == 0

    // Decode edge -> (b, src s, dst d)
    const int b = e / EDGES_PER_MOL;
    const int t = e - b * EDGES_PER_MOL;
    const int s = t / (M_ATOMS - 1);
    const int k = t - s * (M_ATOMS - 1);
    const int d = k + (k >= s ? 1 : 0);
    const int dst = b * M_ATOMS + d;
    const int src = b * M_ATOMS + s;

    // Edge vector (pos fits in L1/L2)
    const float ex = pos[dst * 3 + 0] - pos[src * 3 + 0];
    const float ey = pos[dst * 3 + 1] - pos[src * 3 + 1];
    const float ez = pos[dst * 3 + 2] - pos[src * 3 + 2];
    const float r2 = ex * ex + ey * ey + ez * ez;
    float r = sqrtf(r2);
    r = fmaxf(r, 1e-6f);
    const float inv_r = 1.0f / r;

    // --- RBF: exponential Bernstein x bump cutoff ---
    const float a  = 0.5f * alpha[0];
    const float xx = -a * r;
    const float lp = logf(-expm1f(xx));          // log(1 - e^{xx})
    const float rc  = r * (1.0f / 15.0f);
    const float den = fmaxf((1.0f - rc) * (1.0f + rc), 1e-9f);
    const float fcut = (rc < 1.0f) ? expf(-rc * rc / den) : 0.0f;

    float* row = &sfeat[threadIdx.x * FEAT_W];
    #pragma unroll
    for (int v = 0; v < K_RBF; v++) {
        float logb = g_logbinom[v] + (float)(K_RBF - 1 - v) * xx + (float)v * lp;
        row[v] = fcut * expf(logb);
    }

    // --- Real spherical harmonics (component-normalized, z-up), LMAX=4 ---
    const float x = ex * inv_r, y = ey * inv_r, z = ez * inv_r;

    // C_m + i S_m = (x + i y)^m
    const float C1 = x,               S1 = y;
    const float C2 = C1 * x - S1 * y, S2 = S1 * x + C1 * y;
    const float C3 = C2 * x - S2 * y, S3 = S2 * x + C2 * y;
    const float C4 = C3 * x - S3 * y, S4 = S3 * x + C3 * y;

    // Q_l^m recurrences
    const float Q00 = 1.0f;
    const float Q10 = z;                                      // (2*0+1) z Q00
    const float Q20 = (3.0f * z * Q10 - 1.0f * Q00) * 0.5f;
    const float Q30 = (5.0f * z * Q20 - 2.0f * Q10) * (1.0f / 3.0f);
    const float Q40 = (7.0f * z * Q30 - 3.0f * Q20) * 0.25f;
    const float Q11 = 1.0f;
    const float Q21 = 3.0f * z;                               // (2*1+1) z Q11
    const float Q31 = (5.0f * z * Q21 - 3.0f * Q11) * 0.5f;
    const float Q41 = (7.0f * z * Q31 - 4.0f * Q21) * (1.0f / 3.0f);
    const float Q22 = 3.0f;
    const float Q32 = 5.0f * z * Q22;
    const float Q42 = (7.0f * z * Q32 - 5.0f * Q22) * 0.5f;
    const float Q33 = 15.0f;
    const float Q43 = 7.0f * z * Q33;
    const float Q44 = 105.0f;

    float* sh = row + K_RBF;
    // l=0
    sh[0]  = g_shcoef[0];
    // l=1: m=-1,0,1
    sh[1]  = g_shcoef[1]  * Q11 * S1;
    sh[2]  = g_shcoef[2]  * Q10;
    sh[3]  = g_shcoef[3]  * Q11 * C1;
    // l=2
    sh[4]  = g_shcoef[4]  * Q22 * S2;
    sh[5]  = g_shcoef[5]  * Q21 * S1;
    sh[6]  = g_shcoef[6]  * Q20;
    sh[7]  = g_shcoef[7]  * Q21 * C1;
    sh[8]  = g_shcoef[8]  * Q22 * C2;
    // l=3
    sh[9]  = g_shcoef[9]  * Q33 * S3;
    sh[10] = g_shcoef[10] * Q32 * S2;
    sh[11] = g_shcoef[11] * Q31 * S1;
    sh[12] = g_shcoef[12] * Q30;
    sh[13] = g_shcoef[13] * Q31 * C1;
    sh[14] = g_shcoef[14] * Q32 * C2;
    sh[15] = g_shcoef[15] * Q33 * C3;
    // l=4
    sh[16] = g_shcoef[16] * Q44 * S4;
    sh[17] = g_shcoef[17] * Q43 * S3;
    sh[18] = g_shcoef[18] * Q42 * S2;
    sh[19] = g_shcoef[19] * Q41 * S1;
    sh[20] = g_shcoef[20] * Q40;
    sh[21] = g_shcoef[21] * Q41 * C1;
    sh[22] = g_shcoef[22] * Q42 * C2;
    sh[23] = g_shcoef[23] * Q43 * C3;
    sh[24] = g_shcoef[24] * Q44 * C4;

    // --- edge_index + transpose_index (coalesced) ---
    out[OFF_EI + e]           = (float)dst;
    out[OFF_EI + E_TOTAL + e] = (float)src;
    const int tr = b * EDGES_PER_MOL + d * (M_ATOMS - 1) + s - (d < s ? 1 : 0);
    out[OFF_TR + e] = (float)tr;

    __syncthreads();

    // --- Cooperative coalesced drain of feature rows (float4) ---
    float4* __restrict__ dst4 = (float4*)(out + (size_t)e0 * FEAT_W);  // 29184B blocks, 16B aligned
    const float4* __restrict__ src4 = (const float4*)sfeat;
    #pragma unroll
    for (int i = threadIdx.x; i < (EPB * FEAT_W) / 4; i += EPB) {
        dst4[i] = src4[i];
    }
}

// ---------------------------------------------------------------------------
// Embedding gather: node_emb[n, :] = embed_table[atomic_numbers[n], :]
// float4 per thread; table is 10 KB -> L1 resident.
// ---------------------------------------------------------------------------
__global__ __launch_bounds__(256) void emb_kernel(
    const int* __restrict__ an,
    const float* __restrict__ table,
    float* __restrict__ out)
{
    const int i = blockIdx.x * blockDim.x + threadIdx.x;   // over N*HS/4 = 393216
    const int n = i >> 5;            // 32 float4 per node (HS=128)
    const int h = i & 31;
    const int a = an[n];
    const float4 v = ((const float4*)table)[a * 32 + h];
    ((float4*)(out + OFF_EMB))[i] = v;
}

extern "C" void kernel_launch(void* const* d_in, const int* in_sizes, int n_in,
                              void* d_out, int out_size) {
    const float* pos   = (const float*)d_in[0];
    const int*   an    = (const int*)d_in[1];
    const float* table = (const float*)d_in[2];
    const float* alpha = (const float*)d_in[3];
    float* out = (float*)d_out;

    init_tables_kernel<<<1, 32>>>();
    edge_kernel<<<E_TOTAL / EPB, EPB>>>(pos, alpha, out);
    emb_kernel<<<(N_ATOMS * HS / 4) / 256, 256>>>(an, table, out);
}